// round 14
// baseline (speedup 1.0000x reference)
#include <cuda_runtime.h>
#include <cstddef>

// TensorProduct: out[n,p,n3,f] with parity coupling through CG[9,9,25].
//  - packed fp32x2 (FFMA2); parity butterfly U/V streams (R10-proven math)
//  - CG in smem, duplicated into both halves of a u64 -> broadcast LDS.64
//  - R14: each thread owns TWO channel pairs -> every CG LDS.64 feeds FOUR
//    FFMA2 (breaks R10's LDS:FMA capacity tie, ratio 0.94 -> 0.20).
//    Accumulator registers kept sane by splitting each node's n3 outputs
//    across the block's 4 warps, balanced by CG-nonzero count:
//      w0:[0,5) 319   w1:[5,9) 296   w2:[9,15) 330   w3:[15,25) 280
//  - NO launch-bounds min-blocks forcing (R13 post-mortem: a forced 102-reg
//    cap spilled the accumulators to local memory).

using u64 = unsigned long long;

__device__ __forceinline__ u64 f2mul(u64 a, u64 b) {
    u64 d;
    asm("mul.rn.f32x2 %0, %1, %2;" : "=l"(d) : "l"(a), "l"(b));
    return d;
}
__device__ __forceinline__ u64 f2add(u64 a, u64 b) {
    u64 d;
    asm("add.rn.f32x2 %0, %1, %2;" : "=l"(d) : "l"(a), "l"(b));
    return d;
}
__device__ __forceinline__ u64 f2fma(u64 a, u64 b, u64 c) {
    u64 d;
    asm("fma.rn.f32x2 %0, %1, %2, %3;" : "=l"(d) : "l"(a), "l"(b), "l"(c));
    return d;
}

#define PK_HALF    0x3F0000003F000000ull  // {0.5f, 0.5f}
#define PK_NEGHALF 0xBF000000BF000000ull  // {-0.5f, -0.5f}
#define PK_NEG1    0xBF800000BF800000ull  // {-1.f, -1.f}

static constexpr int LA = 9;
static constexpr int LB = 9;
static constexpr int LC = 25;
static constexpr int FPAIR = 64;    // 128 channels = 64 f32x2 pairs
static constexpr int THREADS = 128; // 1 node: 4 warps x 32 lanes x 2 chpairs

__host__ __device__ constexpr int lval(int idx) { return idx == 0 ? 0 : (idx < 4 ? 1 : 2); }
__host__ __device__ constexpr int imax(int a, int b) { return a > b ? a : b; }
__host__ __device__ constexpr int imin(int a, int b) { return a < b ? a : b; }

// One n3-slice of the tensor product; this thread covers channel pairs
// (lane) and (lane+32). All loop bounds compile-time -> full unroll,
// accumulators in registers, dead (i,j) work DCE'd per slice.
template <int N3B, int N3E>
__device__ __forceinline__ void tp_group(const u64* __restrict__ p0,  // x1 base
                                         const u64* __restrict__ q0,  // x2 base
                                         u64* __restrict__ o0,        // out base
                                         const u64* __restrict__ scg)
{
    constexpr int NA = N3E - N3B;

    // x2 butterfly, both chpairs: s2 = b0+b1, d2 = b0-b1
    u64 s2[2][LB], d2[2][LB];
    #pragma unroll
    for (int j = 0; j < LB; ++j) {
        #pragma unroll
        for (int p = 0; p < 2; ++p) {
            u64 b0 = q0[j * FPAIR + 32 * p];
            u64 b1 = q0[(LB + j) * FPAIR + 32 * p];
            s2[p][j] = f2add(b0, b1);
            d2[p][j] = f2fma(b1, PK_NEG1, b0);
        }
    }

    u64 accU[2][NA], accV[2][NA];
    #pragma unroll
    for (int k = 0; k < NA; ++k) {
        accU[0][k] = 0ull; accV[0][k] = 0ull;
        accU[1][k] = 0ull; accV[1][k] = 0ull;
    }

    #pragma unroll
    for (int i = 0; i < LA; ++i) {
        const int la = lval(i);
        // x1 butterfly on the fly: s1 = 0.5(a0+a1), d1 = 0.5(a0-a1)
        u64 s1[2], d1[2];
        #pragma unroll
        for (int p = 0; p < 2; ++p) {
            u64 a0 = p0[i * FPAIR + 32 * p];
            u64 a1 = p0[(LA + i) * FPAIR + 32 * p];
            u64 h  = f2mul(a0, PK_HALF);
            s1[p]  = f2fma(a1, PK_HALF,    h);
            d1[p]  = f2fma(a1, PK_NEGHALF, h);
        }

        #pragma unroll
        for (int j = 0; j < LB; ++j) {
            const int lb = lval(j);
            const int lo = (la > lb) ? (la - lb) : (lb - la);
            const int hi = la + lb;
            const int S  = imax(lo * lo, N3B);              // compile-time
            const int E  = imin((hi + 1) * (hi + 1), N3E);  // compile-time
            if (S < E) {
                const u64 U0 = f2mul(s1[0], s2[0][j]);
                const u64 V0 = f2mul(d1[0], d2[0][j]);
                const u64 U1 = f2mul(s1[1], s2[1][j]);
                const u64 V1 = f2mul(d1[1], d2[1][j]);
                #pragma unroll
                for (int n3 = S; n3 < E; ++n3) {
                    const u64 c = scg[(i * LB + j) * LC + n3]; // broadcast LDS.64
                    const int k = n3 - N3B;
                    accU[0][k] = f2fma(c, U0, accU[0][k]);
                    accV[0][k] = f2fma(c, V0, accV[0][k]);
                    accU[1][k] = f2fma(c, U1, accU[1][k]);
                    accV[1][k] = f2fma(c, V1, accV[1][k]);
                }
            }
        }
    }

    // butterfly back: even = U+V, odd = U-V
    #pragma unroll
    for (int k = 0; k < NA; ++k) {
        #pragma unroll
        for (int p = 0; p < 2; ++p) {
            o0[(N3B + k) * FPAIR + 32 * p]      = f2add(accU[p][k], accV[p][k]);
            o0[(LC + N3B + k) * FPAIR + 32 * p] = f2fma(accV[p][k], PK_NEG1, accU[p][k]);
        }
    }
}

__global__ __launch_bounds__(THREADS)
void tp_f32x2_kernel(const float* __restrict__ x1,
                     const float* __restrict__ x2,
                     const float* __restrict__ cg,
                     float* __restrict__ out,
                     int n_nodes)
{
    // CG duplicated into both 32-bit halves: LDS.64 -> ready f32x2 operand
    __shared__ u64 scg[LA * LB * LC]; // 2025 * 8B = 16.2 KB

    {
        const unsigned* cgu = reinterpret_cast<const unsigned*>(cg);
        for (int k = threadIdx.x; k < LA * LB * LC; k += THREADS) {
            u64 v = (u64)cgu[k];
            scg[k] = (v << 32) | v;
        }
    }
    __syncthreads();

    const int node = blockIdx.x;
    if (node >= n_nodes) return;

    const int w    = threadIdx.x >> 5;        // warp id 0..3 -> n3 slice
    const int lane = threadIdx.x & 31;        // chpairs (lane, lane+32)

    const u64* x1u = reinterpret_cast<const u64*>(x1);
    const u64* x2u = reinterpret_cast<const u64*>(x2);
    u64*       ou  = reinterpret_cast<u64*>(out);

    const u64* p0 = x1u + ((size_t)node * 2 * LA) * FPAIR + lane;
    const u64* q0 = x2u + ((size_t)node * 2 * LB) * FPAIR + lane;
    u64*       o0 = ou  + ((size_t)node * 2 * LC) * FPAIR + lane;

    if      (w == 0) tp_group<0,  5>(p0, q0, o0, scg);
    else if (w == 1) tp_group<5,  9>(p0, q0, o0, scg);
    else if (w == 2) tp_group<9, 15>(p0, q0, o0, scg);
    else             tp_group<15,25>(p0, q0, o0, scg);
}

extern "C" void kernel_launch(void* const* d_in, const int* in_sizes, int n_in,
                              void* d_out, int out_size)
{
    const float* x1 = (const float*)d_in[0]; // [N, 2, 9, 128]
    const float* x2 = (const float*)d_in[1]; // [N, 2, 9, 128]
    const float* cg = (const float*)d_in[2]; // [9, 9, 25]
    float* out = (float*)d_out;              // [N, 2, 25, 128]

    const int n_nodes = in_sizes[0] / (2 * LA * 128);

    tp_f32x2_kernel<<<n_nodes, THREADS>>>(x1, x2, cg, out, n_nodes);
}

// round 15
// speedup vs baseline: 2.2637x; 2.2637x over previous
#include <cuda_runtime.h>
#include <cstddef>

// TensorProduct: out[n,p,n3,f] with parity coupling through CG[9,9,25].
//  - packed fp32x2 (FFMA2); parity butterfly U/V streams (R10-proven math)
//  - CG in smem, duplicated into both u64 halves -> broadcast LDS.64 operand
//  - R15: 2-way l3 split across warps of one node-block:
//      warps 0-1: n3 [0,9)  (615 coeffs)   warps 2-3: n3 [9,25) (610 coeffs)
//    s1/d1 built on the fly; unused (i,j) rows (l=0 in the g1 half) are
//    skipped at compile time INCLUDING their loads.
//    Register budget engineered to ~120 -> __launch_bounds__(128,4) gives
//    16 warps/SM (R10 had 12) without spilling (R13 post-mortem: cap 102
//    spilled; R14: 206 regs -> 8 warps -> collapse).

using u64 = unsigned long long;

__device__ __forceinline__ u64 f2mul(u64 a, u64 b) {
    u64 d;
    asm("mul.rn.f32x2 %0, %1, %2;" : "=l"(d) : "l"(a), "l"(b));
    return d;
}
__device__ __forceinline__ u64 f2add(u64 a, u64 b) {
    u64 d;
    asm("add.rn.f32x2 %0, %1, %2;" : "=l"(d) : "l"(a), "l"(b));
    return d;
}
__device__ __forceinline__ u64 f2fma(u64 a, u64 b, u64 c) {
    u64 d;
    asm("fma.rn.f32x2 %0, %1, %2, %3;" : "=l"(d) : "l"(a), "l"(b), "l"(c));
    return d;
}

#define PK_HALF    0x3F0000003F000000ull  // {0.5f, 0.5f}
#define PK_NEGHALF 0xBF000000BF000000ull  // {-0.5f, -0.5f}
#define PK_NEG1    0xBF800000BF800000ull  // {-1.f, -1.f}

static constexpr int LA = 9;
static constexpr int LB = 9;
static constexpr int LC = 25;
static constexpr int FPAIR = 64;    // 128 channels = 64 f32x2 pairs
static constexpr int THREADS = 128; // 1 node: 64 chpairs x 2 l3-halves

__host__ __device__ constexpr int lval(int idx) { return idx == 0 ? 0 : (idx < 4 ? 1 : 2); }
__host__ __device__ constexpr int imax(int a, int b) { return a > b ? a : b; }
__host__ __device__ constexpr int imin(int a, int b) { return a < b ? a : b; }

// slot (i or j) contributes to n3 >= N3B for SOME partner l'? max E is with
// partner l'=2: E_max = (lval+2+1)^2. Used iff E_max > N3B.
__host__ __device__ constexpr bool slot_used(int idx, int N3B) {
    return (lval(idx) + 3) * (lval(idx) + 3) > N3B;
}

// One l3-half for one (node, channel-pair) thread.
// G0: n3 [0,9) (l3<=2);  G1: n3 [9,25) (l3>=3).
template <int N3B, int N3E>
__device__ __forceinline__ void tp_half(const u64* __restrict__ p0,  // x1 base
                                        const u64* __restrict__ q0,  // x2 base
                                        u64* __restrict__ o0,        // out base
                                        const u64* __restrict__ scg)
{
    constexpr int NA = N3E - N3B;

    // x2 butterfly, only the j-slots this half can use (loads skipped too)
    u64 s2[LB], d2[LB];
    #pragma unroll
    for (int j = 0; j < LB; ++j) {
        if (slot_used(j, N3B)) {                   // compile-time
            u64 b0 = q0[j * FPAIR];
            u64 b1 = q0[(LB + j) * FPAIR];
            s2[j]  = f2add(b0, b1);                // (b0+b1)
            d2[j]  = f2fma(b1, PK_NEG1, b0);       // (b0-b1)
        }
    }

    u64 accU[NA], accV[NA];
    #pragma unroll
    for (int k = 0; k < NA; ++k) { accU[k] = 0ull; accV[k] = 0ull; }

    #pragma unroll
    for (int i = 0; i < LA; ++i) {
        if (slot_used(i, N3B)) {                   // compile-time
            const int la = lval(i);
            // x1 butterfly on the fly: s1 = 0.5(a0+a1), d1 = 0.5(a0-a1)
            u64 a0 = p0[i * FPAIR];
            u64 a1 = p0[(LA + i) * FPAIR];
            u64 h  = f2mul(a0, PK_HALF);
            u64 s1 = f2fma(a1, PK_HALF,    h);
            u64 d1 = f2fma(a1, PK_NEGHALF, h);

            #pragma unroll
            for (int j = 0; j < LB; ++j) {
                const int lb = lval(j);
                const int lo = (la > lb) ? (la - lb) : (lb - la);
                const int hi = la + lb;
                const int S  = imax(lo * lo, N3B);              // compile-time
                const int E  = imin((hi + 1) * (hi + 1), N3E);  // compile-time
                if (S < E) {
                    const u64 U = f2mul(s1, s2[j]);
                    const u64 V = f2mul(d1, d2[j]);
                    #pragma unroll
                    for (int n3 = S; n3 < E; ++n3) {
                        const u64 c = scg[(i * LB + j) * LC + n3]; // broadcast LDS.64
                        accU[n3 - N3B] = f2fma(c, U, accU[n3 - N3B]);
                        accV[n3 - N3B] = f2fma(c, V, accV[n3 - N3B]);
                    }
                }
            }
        }
    }

    // butterfly back: even = U+V, odd = U-V
    #pragma unroll
    for (int k = 0; k < NA; ++k) {
        o0[(N3B + k) * FPAIR]      = f2add(accU[k], accV[k]);
        o0[(LC + N3B + k) * FPAIR] = f2fma(accV[k], PK_NEG1, accU[k]);
    }
}

__global__ __launch_bounds__(THREADS, 4)
void tp_f32x2_kernel(const float* __restrict__ x1,
                     const float* __restrict__ x2,
                     const float* __restrict__ cg,
                     float* __restrict__ out,
                     int n_nodes)
{
    // CG duplicated into both 32-bit halves: LDS.64 -> ready f32x2 operand
    __shared__ u64 scg[LA * LB * LC]; // 2025 * 8B = 16.2 KB

    {
        const unsigned* cgu = reinterpret_cast<const unsigned*>(cg);
        for (int k = threadIdx.x; k < LA * LB * LC; k += THREADS) {
            u64 v = (u64)cgu[k];
            scg[k] = (v << 32) | v;
        }
    }
    __syncthreads();

    const int node = blockIdx.x;
    if (node >= n_nodes) return;
    const int c = threadIdx.x & (FPAIR - 1);
    const int g = threadIdx.x >> 6;  // warps 0-1 -> g0; warps 2-3 -> g1

    const u64* x1u = reinterpret_cast<const u64*>(x1);
    const u64* x2u = reinterpret_cast<const u64*>(x2);
    u64*       ou  = reinterpret_cast<u64*>(out);

    const u64* p0 = x1u + ((size_t)node * 2 * LA) * FPAIR + c;
    const u64* q0 = x2u + ((size_t)node * 2 * LB) * FPAIR + c;
    u64*       o0 = ou  + ((size_t)node * 2 * LC) * FPAIR + c;

    if (g == 0) tp_half<0,  9>(p0, q0, o0, scg);
    else        tp_half<9, 25>(p0, q0, o0, scg);
}

extern "C" void kernel_launch(void* const* d_in, const int* in_sizes, int n_in,
                              void* d_out, int out_size)
{
    const float* x1 = (const float*)d_in[0]; // [N, 2, 9, 128]
    const float* x2 = (const float*)d_in[1]; // [N, 2, 9, 128]
    const float* cg = (const float*)d_in[2]; // [9, 9, 25]
    float* out = (float*)d_out;              // [N, 2, 25, 128]

    const int n_nodes = in_sizes[0] / (2 * LA * 128);

    tp_f32x2_kernel<<<n_nodes, THREADS>>>(x1, x2, cg, out, n_nodes);
}